// round 14
// baseline (speedup 1.0000x reference)
#include <cuda_runtime.h>

#define N_NODES 50000
#define N_EDGES 800000
#define DIN 128
#define DOUT 64
#define ROWS_PB 64
#define CAP 128                      // max in-degree capacity per node

// Scratch (device globals — no allocation allowed)
__device__ __align__(16) float d_g[N_NODES * DOUT];  // h = x @ W
__device__ int   d_cnt[N_NODES];                     // in-degree / slot cursor
__device__ int   d_slots[N_NODES * CAP];             // src ids, slotted by dst

// packed f32x2 helpers (sm_100+)
#define PK2(d, lo, hi) asm("mov.b64 %0, {%1, %2};" : "=l"(d) : "f"(lo), "f"(hi))
#define FMA2(d, a, b)  asm("fma.rn.f32x2 %0, %1, %2, %0;" : "+l"(d) : "l"(a), "l"(b))
#define UPK2(lo, hi, v) asm("mov.b64 {%0, %1}, %2;" : "=f"(lo), "=f"(hi) : "l"(v))

// Host-side stream/event objects, created once at load time (host-side driver
// objects; no tracked device allocation). Used for capture-legal fork/join.
static cudaStream_t g_s1;
static cudaEvent_t  g_ev_fork, g_ev_join;
namespace {
struct _StreamInit {
    _StreamInit() {
        cudaStreamCreateWithFlags(&g_s1, cudaStreamNonBlocking);
        cudaEventCreateWithFlags(&g_ev_fork, cudaEventDisableTiming);
        cudaEventCreateWithFlags(&g_ev_join, cudaEventDisableTiming);
    }
};
static _StreamInit _stream_init;
}

// ---------------------------------------------------------------------------
// 1) single-pass slotted scatter: d_slots[dst*CAP + pos] = src
// ---------------------------------------------------------------------------
__global__ __launch_bounds__(256) void place_kernel(const int* __restrict__ ei) {
    int t = blockIdx.x * blockDim.x + threadIdx.x;
    const int n4 = N_EDGES / 4;                 // 200000, exact
    if (t < n4) {
        int4 s = reinterpret_cast<const int4*>(ei)[t];
        int4 d = reinterpret_cast<const int4*>(ei + N_EDGES)[t];
        int p0 = atomicAdd(&d_cnt[d.x], 1);
        int p1 = atomicAdd(&d_cnt[d.y], 1);
        int p2 = atomicAdd(&d_cnt[d.z], 1);
        int p3 = atomicAdd(&d_cnt[d.w], 1);
        if (p0 < CAP) d_slots[d.x * CAP + p0] = s.x;
        if (p1 < CAP) d_slots[d.y * CAP + p1] = s.y;
        if (p2 < CAP) d_slots[d.z * CAP + p2] = s.z;
        if (p3 < CAP) d_slots[d.w * CAP + p3] = s.w;
    }
}

// ---------------------------------------------------------------------------
// 2) h = x @ W — 64x64 tile, 128 threads, 8 rows x 4 cols per thread.
//    Row-pair f32x2 packing: FMA2 operand A = (x[r][k], x[r+4][k]),
//    operand B = dup(W[k][c]) shared across all 4 row-pairs.
// ---------------------------------------------------------------------------
__global__ __launch_bounds__(128) void gemm_kernel(const float* __restrict__ x,
                                                   const float* __restrict__ W) {
    __shared__ float4 xs[ROWS_PB][DIN / 4];   // 32 KB
    __shared__ float  Ws[DIN][DOUT];          // 32 KB

    int row0 = blockIdx.x * ROWS_PB;

    for (int i = threadIdx.x; i < DIN * DOUT / 4; i += 128)
        reinterpret_cast<float4*>(&Ws[0][0])[i] = reinterpret_cast<const float4*>(W)[i];

    for (int i = threadIdx.x; i < ROWS_PB * (DIN / 4); i += 128) {
        int r = i >> 5;               // DIN/4 = 32
        int k4 = i & 31;
        int gr = row0 + r;
        xs[r][k4] = (gr < N_NODES) ? reinterpret_cast<const float4*>(x)[gr * 32 + k4]
                                   : make_float4(0.f, 0.f, 0.f, 0.f);
    }
    __syncthreads();

    int tc = threadIdx.x & 15;        // cols tc*4 .. tc*4+3
    int tr = threadIdx.x >> 4;        // 8 row groups x 8 rows

    // acc2[p][c]: lanes = (row tr*8+p, row tr*8+p+4), col tc*4+c
    unsigned long long acc2[4][4];
#pragma unroll
    for (int p = 0; p < 4; p++)
#pragma unroll
        for (int c = 0; c < 4; c++)
            PK2(acc2[p][c], 0.f, 0.f);

#pragma unroll 2
    for (int k4 = 0; k4 < DIN / 4; k4++) {
        float xr[8][4];
#pragma unroll
        for (int j = 0; j < 8; j++)
            *reinterpret_cast<float4*>(xr[j]) = xs[tr * 8 + j][k4];   // 2-way bcast

#pragma unroll
        for (int j = 0; j < 4; j++) {                 // k = k4*4 + j
            float4 wv = *reinterpret_cast<const float4*>(&Ws[k4 * 4 + j][tc * 4]);
            unsigned long long wd[4];
            PK2(wd[0], wv.x, wv.x);
            PK2(wd[1], wv.y, wv.y);
            PK2(wd[2], wv.z, wv.z);
            PK2(wd[3], wv.w, wv.w);
#pragma unroll
            for (int p = 0; p < 4; p++) {
                unsigned long long xp;
                PK2(xp, xr[p][j], xr[p + 4][j]);      // row-pair pack
                FMA2(acc2[p][0], xp, wd[0]);
                FMA2(acc2[p][1], xp, wd[1]);
                FMA2(acc2[p][2], xp, wd[2]);
                FMA2(acc2[p][3], xp, wd[3]);
            }
        }
    }

#pragma unroll
    for (int p = 0; p < 4; p++) {
        float4 olo, ohi;
        UPK2(olo.x, ohi.x, acc2[p][0]);
        UPK2(olo.y, ohi.y, acc2[p][1]);
        UPK2(olo.z, ohi.z, acc2[p][2]);
        UPK2(olo.w, ohi.w, acc2[p][3]);
        int g0 = row0 + tr * 8 + p;
        int g1 = g0 + 4;
        if (g0 < N_NODES)
            *reinterpret_cast<float4*>(&d_g[g0 * DOUT + tc * 4]) = olo;
        if (g1 < N_NODES)
            *reinterpret_cast<float4*>(&d_g[g1 * DOUT + tc * 4]) = ohi;
    }
}

// ---------------------------------------------------------------------------
// 3) fused gather + norm + bias + log_softmax — one warp per dst node.
//    dinv computed on the fly from cnt (no dinv kernel).
// ---------------------------------------------------------------------------
__global__ __launch_bounds__(256) void gather_final_kernel(const float* __restrict__ b,
                                                           float* __restrict__ out) {
    int warp = (blockIdx.x * blockDim.x + threadIdx.x) >> 5;
    int lane = threadIdx.x & 31;
    if (warp >= N_NODES) return;

    int deg = d_cnt[warp];
    if (deg > CAP) deg = CAP;
    float di = rsqrtf((float)deg + 1.0f);
    const int* slots = d_slots + warp * CAP;
    int base = warp * DOUT + lane * 2;

    float2 hs = *reinterpret_cast<const float2*>(d_g + base);    // self loop
    float2 acc = make_float2(di * hs.x, di * hs.y);

    int j = 0;
    for (; j + 4 <= deg; j += 4) {
        int s0 = __ldg(&slots[j + 0]);
        int s1 = __ldg(&slots[j + 1]);
        int s2 = __ldg(&slots[j + 2]);
        int s3 = __ldg(&slots[j + 3]);
        float w0 = rsqrtf((float)__ldg(&d_cnt[s0]) + 1.0f);
        float w1 = rsqrtf((float)__ldg(&d_cnt[s1]) + 1.0f);
        float w2 = rsqrtf((float)__ldg(&d_cnt[s2]) + 1.0f);
        float w3 = rsqrtf((float)__ldg(&d_cnt[s3]) + 1.0f);
        float2 a0 = *reinterpret_cast<const float2*>(d_g + s0 * DOUT + lane * 2);
        float2 a1 = *reinterpret_cast<const float2*>(d_g + s1 * DOUT + lane * 2);
        float2 a2 = *reinterpret_cast<const float2*>(d_g + s2 * DOUT + lane * 2);
        float2 a3 = *reinterpret_cast<const float2*>(d_g + s3 * DOUT + lane * 2);
        acc.x = fmaf(a0.x, w0, acc.x); acc.y = fmaf(a0.y, w0, acc.y);
        acc.x = fmaf(a1.x, w1, acc.x); acc.y = fmaf(a1.y, w1, acc.y);
        acc.x = fmaf(a2.x, w2, acc.x); acc.y = fmaf(a2.y, w2, acc.y);
        acc.x = fmaf(a3.x, w3, acc.x); acc.y = fmaf(a3.y, w3, acc.y);
    }
    for (; j < deg; j++) {
        int s = __ldg(&slots[j]);
        float w = rsqrtf((float)__ldg(&d_cnt[s]) + 1.0f);
        float2 a = *reinterpret_cast<const float2*>(d_g + s * DOUT + lane * 2);
        acc.x = fmaf(a.x, w, acc.x);
        acc.y = fmaf(a.y, w, acc.y);
    }

    float2 bv = *reinterpret_cast<const float2*>(b + lane * 2);
    float v0 = fmaf(di, acc.x, bv.x);
    float v1 = fmaf(di, acc.y, bv.y);

    float m = fmaxf(v0, v1);
#pragma unroll
    for (int o = 16; o; o >>= 1) m = fmaxf(m, __shfl_xor_sync(0xffffffffu, m, o));
    float s = expf(v0 - m) + expf(v1 - m);
#pragma unroll
    for (int o = 16; o; o >>= 1) s += __shfl_xor_sync(0xffffffffu, s, o);
    float l = m + logf(s);

    float2 o2 = make_float2(v0 - l, v1 - l);
    *reinterpret_cast<float2*>(out + base) = o2;
}

// ---------------------------------------------------------------------------
extern "C" void kernel_launch(void* const* d_in, const int* in_sizes, int n_in,
                              void* d_out, int out_size) {
    const float* x  = (const float*)d_in[0];
    const int*   ei = (const int*)d_in[1];   // JAX default x64-off: int32
    const float* W  = (const float*)d_in[2];
    const float* b  = (const float*)d_in[3];
    float*       out = (float*)d_out;

    // Fork: gemm (h = x@W) on side stream, edge/slot chain on main stream.
    cudaEventRecord(g_ev_fork, 0);
    cudaStreamWaitEvent(g_s1, g_ev_fork, 0);
    gemm_kernel<<<(N_NODES + ROWS_PB - 1) / ROWS_PB, 128, 0, g_s1>>>(x, W);
    cudaEventRecord(g_ev_join, g_s1);

    // zero cnt via graph memset node (capture-legal, no kernel launch cost)
    void* cnt_ptr = nullptr;
    cudaGetSymbolAddress(&cnt_ptr, d_cnt);
    cudaMemsetAsync(cnt_ptr, 0, N_NODES * sizeof(int), 0);
    place_kernel<<<(N_EDGES / 4 + 255) / 256, 256>>>(ei);

    // Join: gather needs both h (side stream) and slots/cnt (main stream).
    cudaStreamWaitEvent(0, g_ev_join, 0);
    gather_final_kernel<<<(N_NODES * 32 + 255) / 256, 256>>>(b, out);
}

// round 15
// speedup vs baseline: 1.1746x; 1.1746x over previous
#include <cuda_runtime.h>

#define N_NODES 50000
#define N_EDGES 800000
#define DIN 128
#define DOUT 64
#define ROWS_PB 64
#define CAP 128                      // max in-degree capacity per node

// Scratch (device globals — no allocation allowed)
__device__ __align__(16) float d_g[N_NODES * DOUT];  // h = x @ W
__device__ int   d_cnt[N_NODES];                     // in-degree / slot cursor
__device__ int   d_slots[N_NODES * CAP];             // src ids, slotted by dst

// packed f32x2 helpers (sm_100+)
#define PK2(d, lo, hi) asm("mov.b64 %0, {%1, %2};" : "=l"(d) : "f"(lo), "f"(hi))
#define FMA2(d, a, b)  asm("fma.rn.f32x2 %0, %1, %2, %0;" : "+l"(d) : "l"(a), "l"(b))
#define UPK2(lo, hi, v) asm("mov.b64 {%0, %1}, %2;" : "=f"(lo), "=f"(hi) : "l"(v))

// Host-side stream/event objects, created once at load time (host-side driver
// objects; no tracked device allocation). Used for capture-legal fork/join.
static cudaStream_t g_s1;
static cudaEvent_t  g_ev_fork, g_ev_join;
namespace {
struct _StreamInit {
    _StreamInit() {
        cudaStreamCreateWithFlags(&g_s1, cudaStreamNonBlocking);
        cudaEventCreateWithFlags(&g_ev_fork, cudaEventDisableTiming);
        cudaEventCreateWithFlags(&g_ev_join, cudaEventDisableTiming);
    }
};
static _StreamInit _stream_init;
}

// ---------------------------------------------------------------------------
// 1) single-pass slotted scatter: d_slots[dst*CAP + pos] = src
// ---------------------------------------------------------------------------
__global__ __launch_bounds__(256) void place_kernel(const int* __restrict__ ei) {
    int t = blockIdx.x * blockDim.x + threadIdx.x;
    const int n4 = N_EDGES / 4;                 // 200000, exact
    if (t < n4) {
        int4 s = reinterpret_cast<const int4*>(ei)[t];
        int4 d = reinterpret_cast<const int4*>(ei + N_EDGES)[t];
        int p0 = atomicAdd(&d_cnt[d.x], 1);
        int p1 = atomicAdd(&d_cnt[d.y], 1);
        int p2 = atomicAdd(&d_cnt[d.z], 1);
        int p3 = atomicAdd(&d_cnt[d.w], 1);
        if (p0 < CAP) d_slots[d.x * CAP + p0] = s.x;
        if (p1 < CAP) d_slots[d.y * CAP + p1] = s.y;
        if (p2 < CAP) d_slots[d.z * CAP + p2] = s.z;
        if (p3 < CAP) d_slots[d.w * CAP + p3] = s.w;
    }
}

// ---------------------------------------------------------------------------
// 2) h = x @ W — 64x64 tile, 256 threads, 4 rows x 4 cols per thread,
//    packed fma.rn.f32x2 (column pairs). Measured-best formulation (R13).
// ---------------------------------------------------------------------------
__global__ __launch_bounds__(256) void gemm_kernel(const float* __restrict__ x,
                                                   const float* __restrict__ W) {
    __shared__ float4 xs[ROWS_PB][DIN / 4];   // 32 KB
    __shared__ float  Ws[DIN][DOUT];          // 32 KB

    int row0 = blockIdx.x * ROWS_PB;

    for (int i = threadIdx.x; i < DIN * DOUT / 4; i += 256)
        reinterpret_cast<float4*>(&Ws[0][0])[i] = reinterpret_cast<const float4*>(W)[i];

    for (int i = threadIdx.x; i < ROWS_PB * (DIN / 4); i += 256) {
        int r = i >> 5;
        int k4 = i & 31;
        int gr = row0 + r;
        xs[r][k4] = (gr < N_NODES) ? reinterpret_cast<const float4*>(x)[gr * 32 + k4]
                                   : make_float4(0.f, 0.f, 0.f, 0.f);
    }
    __syncthreads();

    int tc = threadIdx.x & 15;
    int tr = threadIdx.x >> 4;

    unsigned long long acc2[4][2];
#pragma unroll
    for (int r = 0; r < 4; r++) {
        PK2(acc2[r][0], 0.f, 0.f);
        PK2(acc2[r][1], 0.f, 0.f);
    }

#pragma unroll 4
    for (int k4 = 0; k4 < DIN / 4; k4++) {
        float xr[4][4];
        *reinterpret_cast<float4*>(xr[0]) = xs[tr * 4 + 0][k4];
        *reinterpret_cast<float4*>(xr[1]) = xs[tr * 4 + 1][k4];
        *reinterpret_cast<float4*>(xr[2]) = xs[tr * 4 + 2][k4];
        *reinterpret_cast<float4*>(xr[3]) = xs[tr * 4 + 3][k4];

#pragma unroll
        for (int j = 0; j < 4; j++) {
            float4 wv = *reinterpret_cast<const float4*>(&Ws[k4 * 4 + j][tc * 4]);
            unsigned long long wlo, whi;
            PK2(wlo, wv.x, wv.y);
            PK2(whi, wv.z, wv.w);
#pragma unroll
            for (int r = 0; r < 4; r++) {
                unsigned long long xd;
                PK2(xd, xr[r][j], xr[r][j]);
                FMA2(acc2[r][0], xd, wlo);
                FMA2(acc2[r][1], xd, whi);
            }
        }
    }

#pragma unroll
    for (int r = 0; r < 4; r++) {
        int lr = tr * 4 + r;
        int gr = row0 + lr;
        if (gr < N_NODES) {
            float4 o;
            UPK2(o.x, o.y, acc2[r][0]);
            UPK2(o.z, o.w, acc2[r][1]);
            *reinterpret_cast<float4*>(&d_g[gr * DOUT + tc * 4]) = o;
        }
    }
}

// ---------------------------------------------------------------------------
// 3) fused gather + norm + bias + log_softmax — one warp per dst node.
//    dinv computed on the fly from cnt.
// ---------------------------------------------------------------------------
__global__ __launch_bounds__(256) void gather_final_kernel(const float* __restrict__ b,
                                                           float* __restrict__ out) {
    int warp = (blockIdx.x * blockDim.x + threadIdx.x) >> 5;
    int lane = threadIdx.x & 31;
    if (warp >= N_NODES) return;

    int deg = d_cnt[warp];
    if (deg > CAP) deg = CAP;
    float di = rsqrtf((float)deg + 1.0f);
    const int* slots = d_slots + warp * CAP;
    int base = warp * DOUT + lane * 2;

    float2 hs = *reinterpret_cast<const float2*>(d_g + base);    // self loop
    float2 acc = make_float2(di * hs.x, di * hs.y);

    int j = 0;
    for (; j + 4 <= deg; j += 4) {
        int s0 = __ldg(&slots[j + 0]);
        int s1 = __ldg(&slots[j + 1]);
        int s2 = __ldg(&slots[j + 2]);
        int s3 = __ldg(&slots[j + 3]);
        float w0 = rsqrtf((float)__ldg(&d_cnt[s0]) + 1.0f);
        float w1 = rsqrtf((float)__ldg(&d_cnt[s1]) + 1.0f);
        float w2 = rsqrtf((float)__ldg(&d_cnt[s2]) + 1.0f);
        float w3 = rsqrtf((float)__ldg(&d_cnt[s3]) + 1.0f);
        float2 a0 = *reinterpret_cast<const float2*>(d_g + s0 * DOUT + lane * 2);
        float2 a1 = *reinterpret_cast<const float2*>(d_g + s1 * DOUT + lane * 2);
        float2 a2 = *reinterpret_cast<const float2*>(d_g + s2 * DOUT + lane * 2);
        float2 a3 = *reinterpret_cast<const float2*>(d_g + s3 * DOUT + lane * 2);
        acc.x = fmaf(a0.x, w0, acc.x); acc.y = fmaf(a0.y, w0, acc.y);
        acc.x = fmaf(a1.x, w1, acc.x); acc.y = fmaf(a1.y, w1, acc.y);
        acc.x = fmaf(a2.x, w2, acc.x); acc.y = fmaf(a2.y, w2, acc.y);
        acc.x = fmaf(a3.x, w3, acc.x); acc.y = fmaf(a3.y, w3, acc.y);
    }
    for (; j < deg; j++) {
        int s = __ldg(&slots[j]);
        float w = rsqrtf((float)__ldg(&d_cnt[s]) + 1.0f);
        float2 a = *reinterpret_cast<const float2*>(d_g + s * DOUT + lane * 2);
        acc.x = fmaf(a.x, w, acc.x);
        acc.y = fmaf(a.y, w, acc.y);
    }

    float2 bv = *reinterpret_cast<const float2*>(b + lane * 2);
    float v0 = fmaf(di, acc.x, bv.x);
    float v1 = fmaf(di, acc.y, bv.y);

    float m = fmaxf(v0, v1);
#pragma unroll
    for (int o = 16; o; o >>= 1) m = fmaxf(m, __shfl_xor_sync(0xffffffffu, m, o));
    float s = expf(v0 - m) + expf(v1 - m);
#pragma unroll
    for (int o = 16; o; o >>= 1) s += __shfl_xor_sync(0xffffffffu, s, o);
    float l = m + logf(s);

    float2 o2 = make_float2(v0 - l, v1 - l);
    *reinterpret_cast<float2*>(out + base) = o2;
}

// ---------------------------------------------------------------------------
extern "C" void kernel_launch(void* const* d_in, const int* in_sizes, int n_in,
                              void* d_out, int out_size) {
    const float* x  = (const float*)d_in[0];
    const int*   ei = (const int*)d_in[1];   // JAX default x64-off: int32
    const float* W  = (const float*)d_in[2];
    const float* b  = (const float*)d_in[3];
    float*       out = (float*)d_out;

    // Fork: gemm (h = x@W) on side stream, edge/slot chain on main stream.
    cudaEventRecord(g_ev_fork, 0);
    cudaStreamWaitEvent(g_s1, g_ev_fork, 0);
    gemm_kernel<<<(N_NODES + ROWS_PB - 1) / ROWS_PB, 256, 0, g_s1>>>(x, W);
    cudaEventRecord(g_ev_join, g_s1);

    // zero cnt via graph memset node (capture-legal, no kernel launch cost)
    void* cnt_ptr = nullptr;
    cudaGetSymbolAddress(&cnt_ptr, d_cnt);
    cudaMemsetAsync(cnt_ptr, 0, N_NODES * sizeof(int), 0);
    place_kernel<<<(N_EDGES / 4 + 255) / 256, 256>>>(ei);

    // Join: gather needs both h (side stream) and slots/cnt (main stream).
    cudaStreamWaitEvent(0, g_ev_join, 0);
    gather_final_kernel<<<(N_NODES * 32 + 255) / 256, 256>>>(b, out);
}